// round 15
// baseline (speedup 1.0000x reference)
#include <cuda_runtime.h>
#include <cstdint>
#include <math.h>

#define T_MAX 1000
#define B_ 64
#define D_ 128
#define N_ 512
#define O_ 10

#define SIM_BLKS 8       // 8 blocks x 8 warps = 64 batches (1 warp per batch)
#define TP_BLKS 256
#define FULLM 0xffffffffu

__device__ float g_Iext[(size_t)T_MAX * B_ * N_];  // 131 MB scratch
__device__ float g_WT[N_ * N_];                    // W_rec transposed
__device__ unsigned g_cnt[512];                    // per-M-tile gemm completion (4 each)
__device__ unsigned g_tp;                          // transpose done counter

__global__ void reset_kernel() {
    int i = threadIdx.x;
    if (i < 512) g_cnt[i] = 0u;
    if (i == 0) g_tp = 0u;
}

__device__ __forceinline__ unsigned ldacq(const unsigned* p) {
    unsigned v;
    asm volatile("ld.acquire.gpu.u32 %0, [%1];" : "=r"(v) : "l"(p));
    return v;
}

// warp-level: spin until g_cnt[xbase .. xbase+nx-1] all >= 4 (x > xmax exempt)
__device__ __forceinline__ void verify_w(int lane, int xbase, int nx, int xmax) {
    int x = xbase + lane;
    bool need = (lane < nx) && (x <= xmax);
    for (;;) {
        bool ok = !need || (ldacq(&g_cnt[x]) >= 4u);
        if (__ballot_sync(FULLM, ok) == FULLM) break;
        __nanosleep(64);
    }
}

__device__ __forceinline__ void mma_tf32(float& c0, float& c1, float& c2, float& c3,
                                         uint32_t a0, uint32_t a1, uint32_t a2, uint32_t a3,
                                         uint32_t b0, uint32_t b1) {
    asm volatile(
        "mma.sync.aligned.m16n8k8.row.col.f32.tf32.tf32.f32 "
        "{%0,%1,%2,%3}, {%4,%5,%6,%7}, {%8,%9}, {%0,%1,%2,%3};"
        : "+f"(c0), "+f"(c1), "+f"(c2), "+f"(c3)
        : "r"(a0), "r"(a1), "r"(a2), "r"(a3), "r"(b0), "r"(b1));
}

__device__ __forceinline__ uint32_t f2tf32(float x) {
    uint32_t r;
    asm("cvt.rna.tf32.f32 %0, %1;" : "=r"(r) : "f"(x));
    return r;
}

// ---------------- GEMM tile geometry (round-11 proven config) ----------------
#define TLD 132
#define GEMM_DSMEM (2 * 128 * TLD * 4)

__global__ __launch_bounds__(256, 1) void mega(
    const float* __restrict__ X, const float* __restrict__ Win,
    const float* __restrict__ sc_p, const float* __restrict__ Wrec,
    const float* __restrict__ Wout, const float* __restrict__ bout,
    const float* __restrict__ osc_p,
    float* __restrict__ out, float* __restrict__ spk, float* __restrict__ vlt,
    float* __restrict__ pscO, float* __restrict__ filt,
    int T, int startT, int writeHist,
    float e_syn, float e_asc, float alpha)
{
    const int bid = blockIdx.x;
    const int tid = threadIdx.x;
    const int BN = B_ * N_;
    const int NG = (T / 2) * 4;

    // ================= GEMM role (mma.sync tf32, full-K) =================
    if (bid >= SIM_BLKS && bid < SIM_BLKS + NG) {
        extern __shared__ float sm[];
        uint32_t* As = (uint32_t*)sm;
        uint32_t* Bs = (uint32_t*)(sm + 128 * TLD);

        const int idg = bid - SIM_BLKS;
        const int x = idg >> 2;
        const int y = idg & 3;
        const int m0 = x * 128;
        const int n0 = y * 128;
        const int wrp = tid >> 5, lane = tid & 31;

        const float sc = __ldg(sc_p);
#pragma unroll
        for (int p = 0; p < 16; ++p) {
            int id = tid + p * 256;
            int m = id >> 5;
            int c4 = (id & 31) * 4;
            float4 xv = *(const float4*)(X + (size_t)(m0 + m) * D_ + c4);
            uint32_t* ar = As + m * TLD + c4;
            ar[0] = f2tf32(xv.x * sc); ar[1] = f2tf32(xv.y * sc);
            ar[2] = f2tf32(xv.z * sc); ar[3] = f2tf32(xv.w * sc);
            float4 wv = *(const float4*)(Win + (size_t)(n0 + m) * D_ + c4);
            uint32_t* br = Bs + m * TLD + c4;
            br[0] = f2tf32(wv.x); br[1] = f2tf32(wv.y);
            br[2] = f2tf32(wv.z); br[3] = f2tf32(wv.w);
        }
        __syncthreads();

        const int mw = (wrp & 3) * 32;
        const int nw = (wrp >> 2) * 64;
        const int lr = lane >> 2;
        const int lc = lane & 3;

        float c[2][8][4];
#pragma unroll
        for (int i = 0; i < 2; ++i)
#pragma unroll
            for (int j = 0; j < 8; ++j)
#pragma unroll
                for (int q = 0; q < 4; ++q) c[i][j][q] = 0.f;

#pragma unroll 1
        for (int kk = 0; kk < 16; ++kk) {
            const int k0 = kk * 8;
            uint32_t a[2][4];
#pragma unroll
            for (int i = 0; i < 2; ++i) {
                const uint32_t* ap = As + (mw + i * 16 + lr) * TLD + k0 + lc;
                a[i][0] = ap[0];
                a[i][1] = ap[8 * TLD];
                a[i][2] = ap[4];
                a[i][3] = ap[8 * TLD + 4];
            }
            uint32_t b[8][2];
#pragma unroll
            for (int j = 0; j < 8; ++j) {
                const uint32_t* bp = Bs + (nw + j * 8 + lr) * TLD + k0 + lc;
                b[j][0] = bp[0];
                b[j][1] = bp[4];
            }
#pragma unroll
            for (int i = 0; i < 2; ++i)
#pragma unroll
                for (int j = 0; j < 8; ++j)
                    mma_tf32(c[i][j][0], c[i][j][1], c[i][j][2], c[i][j][3],
                             a[i][0], a[i][1], a[i][2], a[i][3], b[j][0], b[j][1]);
        }

#pragma unroll
        for (int i = 0; i < 2; ++i) {
            const int r0 = m0 + mw + i * 16 + lr;
#pragma unroll
            for (int j = 0; j < 8; ++j) {
                const int col = n0 + nw + j * 8 + lc * 2;
                *(float2*)(g_Iext + (size_t)r0 * N_ + col) = make_float2(c[i][j][0], c[i][j][1]);
                *(float2*)(g_Iext + (size_t)(r0 + 8) * N_ + col) = make_float2(c[i][j][2], c[i][j][3]);
            }
        }
        __threadfence();
        __syncthreads();
        if (tid == 0) atomicAdd(&g_cnt[x], 1u);
        return;
    }

    // ================= transpose role (needed only on spikes) =================
    if (bid >= SIM_BLKS + NG) {
        __shared__ float tile[32][33];
        const int id2 = bid - SIM_BLKS - NG;
        const int bx = (id2 & 15) * 32, by = (id2 >> 4) * 32;
        const int tx = tid & 31, ty = tid >> 5;
#pragma unroll
        for (int i = 0; i < 32; i += 8)
            tile[ty + i][tx] = Wrec[(size_t)(by + ty + i) * N_ + (bx + tx)];
        __syncthreads();
#pragma unroll
        for (int i = 0; i < 32; i += 8)
            g_WT[(size_t)(bx + ty + i) * N_ + (by + tx)] = tile[tx][ty + i];
        __threadfence();
        __syncthreads();
        if (tid == 0) atomicAdd(&g_tp, 1u);
        return;
    }

    // ===== sim role: 1 WARP per batch (8 blocks x 8 warps = 64), barrier-free =====
    {
        const int wrp = tid >> 5, lane = tid & 31;
        const int b = bid * 8 + wrp;          // bijective: 0..63
        const int xmax = ((T - 1) >> 1);

        const float a_mem = 0.05f, VR = -60.0f, VTH = -45.0f, KP = 0.2f, AA = -0.2f;
        const float oma = 1.0f - alpha;

        // neuron i = g*4+q  ->  global neuron id = g*128 + lane*4 + q
        float v[16], asc[16], rr[16], psc[16], f[16], fs[16];
        int rcnt[16];
#pragma unroll
        for (int i = 0; i < 16; ++i) {
            v[i] = VR; asc[i] = 0.f; rr[i] = 0.f; psc[i] = 0.f;
            f[i] = 0.f; fs[i] = 0.f; rcnt[i] = 0;
        }
        const float* Ibase = g_Iext + (size_t)b * N_ + (lane << 2);

        verify_w(lane, 0, 8, xmax);

        float4 pre[2][4];
#pragma unroll
        for (int j = 0; j < 2; ++j)
#pragma unroll
            for (int g = 0; g < 4; ++g)
                pre[j][g] = (j < T) ? *(const float4*)(Ibase + (size_t)j * BN + (g << 7))
                                    : make_float4(0.f, 0.f, 0.f, 0.f);

        unsigned pm = 0;     // my 16 spike bits from previous step
        int cool = 0;        // warp-uniform: >0 while any refractory may be active
        int ever = 0;
        const int Tm = T & ~7;

        for (int t0 = 0; t0 < Tm; t0 += 8) {
            verify_w(lane, (t0 >> 1) + 8, 4, xmax);
#pragma unroll
            for (int jj = 0; jj < 8; ++jj) {
                const int t = t0 + jj;
                float Iv[16];
#pragma unroll
                for (int g = 0; g < 4; ++g) {
                    float4 p4 = pre[jj & 1][g];
                    Iv[g * 4 + 0] = p4.x; Iv[g * 4 + 1] = p4.y;
                    Iv[g * 4 + 2] = p4.z; Iv[g * 4 + 3] = p4.w;
                }
                if (t + 2 < T) {
#pragma unroll
                    for (int g = 0; g < 4; ++g)
                        pre[jj & 1][g] = *(const float4*)(Ibase + (size_t)(t + 2) * BN + (g << 7));
                }

                // recurrent input from previous-step spikes (warp-collective, rare)
                unsigned lw = __ballot_sync(FULLM, pm != 0u);
                if (lw) {
                    float recv[16];
#pragma unroll
                    for (int i = 0; i < 16; ++i) recv[i] = 0.f;
                    do {
                        int l = __ffs((int)lw) - 1;
                        lw &= lw - 1;
                        unsigned m = __shfl_sync(FULLM, pm, l);
                        while (m) {
                            int bp = __ffs((int)m) - 1;
                            m &= m - 1;
                            int spiker = ((bp >> 2) << 7) + (l << 2) + (bp & 3);
                            const float* col = g_WT + (size_t)spiker * N_ + (lane << 2);
#pragma unroll
                            for (int g = 0; g < 4; ++g) {
                                float4 wv = *(const float4*)(col + (g << 7));
                                recv[g * 4 + 0] += wv.x; recv[g * 4 + 1] += wv.y;
                                recv[g * 4 + 2] += wv.z; recv[g * 4 + 3] += wv.w;
                            }
                        }
                    } while (lw);
#pragma unroll
                    for (int i = 0; i < 16; ++i) rr[i] = rr[i] * e_syn + recv[i];
                } else {
#pragma unroll
                    for (int i = 0; i < 16; ++i) rr[i] *= e_syn;
                }

                unsigned mym = 0;
                float sv[16];
#pragma unroll
                for (int i = 0; i < 16; ++i) {
                    psc[i] = psc[i] * e_syn + KP * rr[i];
                    v[i] = v[i] + a_mem * (VR - v[i]) + a_mem * (Iv[i] + psc[i] + asc[i]);
                    bool inref = false;
                    if (cool) { inref = rcnt[i] > 0; if (inref) v[i] = VR; }
                    float s = (!inref && v[i] >= VTH) ? 1.0f : 0.0f;
                    if (s != 0.0f) { v[i] = VR; mym |= 1u << i; }
                    sv[i] = s;
                    asc[i] = asc[i] * e_asc + AA * s;
                    f[i] = (t == 0) ? s : (alpha * f[i] + oma * s);
                    if (t >= startT) fs[i] += f[i];
                }

                unsigned anyb = __ballot_sync(FULLM, mym != 0u);
                if (anyb && !ever) {         // first spike: g_WT must be ready
                    while (ldacq(&g_tp) < (unsigned)TP_BLKS) __nanosleep(64);
                    ever = 1;
                }
                if (anyb | (unsigned)cool) {
#pragma unroll
                    for (int i = 0; i < 16; ++i) {
                        int rm1 = rcnt[i] - 1;
                        rcnt[i] = ((mym >> i) & 1u) ? 5 : (rm1 > 0 ? rm1 : 0);
                    }
                    cool = anyb ? 6 : (cool - 1);
                }
                pm = mym;

                if (writeHist) {
                    size_t idx = (size_t)t * BN + (size_t)b * N_ + (lane << 2);
#pragma unroll
                    for (int g = 0; g < 4; ++g) {
                        int i0 = g * 4;
                        size_t o = idx + ((size_t)g << 7);
                        *(float4*)(vlt + o)  = make_float4(v[i0], v[i0+1], v[i0+2], v[i0+3]);
                        *(float4*)(spk + o)  = make_float4(sv[i0], sv[i0+1], sv[i0+2], sv[i0+3]);
                        *(float4*)(pscO + o) = make_float4(psc[i0], psc[i0+1], psc[i0+2], psc[i0+3]);
                        *(float4*)(filt + o) = make_float4(f[i0], f[i0+1], f[i0+2], f[i0+3]);
                    }
                }
            }
        }

        // remainder steps (T % 8)
        if (Tm < T) {
            verify_w(lane, Tm >> 1, ((T - 1) >> 1) - (Tm >> 1) + 1, xmax);
            for (int t = Tm; t < T; ++t) {
                float Iv[16];
#pragma unroll
                for (int g = 0; g < 4; ++g) {
                    float4 p4 = *(const float4*)(Ibase + (size_t)t * BN + (g << 7));
                    Iv[g * 4 + 0] = p4.x; Iv[g * 4 + 1] = p4.y;
                    Iv[g * 4 + 2] = p4.z; Iv[g * 4 + 3] = p4.w;
                }
                unsigned lw = __ballot_sync(FULLM, pm != 0u);
                if (lw) {
                    float recv[16];
#pragma unroll
                    for (int i = 0; i < 16; ++i) recv[i] = 0.f;
                    do {
                        int l = __ffs((int)lw) - 1;
                        lw &= lw - 1;
                        unsigned m = __shfl_sync(FULLM, pm, l);
                        while (m) {
                            int bp = __ffs((int)m) - 1;
                            m &= m - 1;
                            int spiker = ((bp >> 2) << 7) + (l << 2) + (bp & 3);
                            const float* col = g_WT + (size_t)spiker * N_ + (lane << 2);
#pragma unroll
                            for (int g = 0; g < 4; ++g) {
                                float4 wv = *(const float4*)(col + (g << 7));
                                recv[g * 4 + 0] += wv.x; recv[g * 4 + 1] += wv.y;
                                recv[g * 4 + 2] += wv.z; recv[g * 4 + 3] += wv.w;
                            }
                        }
                    } while (lw);
#pragma unroll
                    for (int i = 0; i < 16; ++i) rr[i] = rr[i] * e_syn + recv[i];
                } else {
#pragma unroll
                    for (int i = 0; i < 16; ++i) rr[i] *= e_syn;
                }
                unsigned mym = 0;
                float sv[16];
#pragma unroll
                for (int i = 0; i < 16; ++i) {
                    psc[i] = psc[i] * e_syn + KP * rr[i];
                    v[i] = v[i] + a_mem * (VR - v[i]) + a_mem * (Iv[i] + psc[i] + asc[i]);
                    bool inref = false;
                    if (cool) { inref = rcnt[i] > 0; if (inref) v[i] = VR; }
                    float s = (!inref && v[i] >= VTH) ? 1.0f : 0.0f;
                    if (s != 0.0f) { v[i] = VR; mym |= 1u << i; }
                    sv[i] = s;
                    asc[i] = asc[i] * e_asc + AA * s;
                    f[i] = (t == 0) ? s : (alpha * f[i] + oma * s);
                    if (t >= startT) fs[i] += f[i];
                }
                unsigned anyb = __ballot_sync(FULLM, mym != 0u);
                if (anyb && !ever) {
                    while (ldacq(&g_tp) < (unsigned)TP_BLKS) __nanosleep(64);
                    ever = 1;
                }
                if (anyb | (unsigned)cool) {
#pragma unroll
                    for (int i = 0; i < 16; ++i) {
                        int rm1 = rcnt[i] - 1;
                        rcnt[i] = ((mym >> i) & 1u) ? 5 : (rm1 > 0 ? rm1 : 0);
                    }
                    cool = anyb ? 6 : (cool - 1);
                }
                pm = mym;
                if (writeHist) {
                    size_t idx = (size_t)t * BN + (size_t)b * N_ + (lane << 2);
#pragma unroll
                    for (int g = 0; g < 4; ++g) {
                        int i0 = g * 4;
                        size_t o = idx + ((size_t)g << 7);
                        *(float4*)(vlt + o)  = make_float4(v[i0], v[i0+1], v[i0+2], v[i0+3]);
                        *(float4*)(spk + o)  = make_float4(sv[i0], sv[i0+1], sv[i0+2], sv[i0+3]);
                        *(float4*)(pscO + o) = make_float4(psc[i0], psc[i0+1], psc[i0+2], psc[i0+3]);
                        *(float4*)(filt + o) = make_float4(f[i0], f[i0+1], f[i0+2], f[i0+3]);
                    }
                }
            }
        }

        // readout (warp-local)
        const float inv = __ldg(osc_p) / (float)(T - startT);
        float a[16];
#pragma unroll
        for (int i = 0; i < 16; ++i) a[i] = fs[i] * inv;
#pragma unroll 1
        for (int o = 0; o < O_; ++o) {
            float val = 0.f;
#pragma unroll
            for (int g = 0; g < 4; ++g) {
                float4 w4 = *(const float4*)(Wout + (size_t)o * N_ + (g << 7) + (lane << 2));
                int i0 = g * 4;
                val += a[i0] * w4.x + a[i0+1] * w4.y + a[i0+2] * w4.z + a[i0+3] * w4.w;
            }
#pragma unroll
            for (int off = 16; off > 0; off >>= 1)
                val += __shfl_down_sync(FULLM, val, off);
            if (lane == 0) out[b * O_ + o] = val + __ldg(bout + o);
        }
    }
}

extern "C" void kernel_launch(void* const* d_in, const int* in_sizes, int n_in,
                              void* d_out, int out_size) {
    const float* x    = (const float*)d_in[0];
    const float* Win  = (const float*)d_in[1];
    const float* isc  = (const float*)d_in[2];
    const float* Wrec = (const float*)d_in[3];
    const float* Wout = (const float*)d_in[4];
    const float* bout = (const float*)d_in[5];
    const float* osc  = (const float*)d_in[6];

    const int T = in_sizes[0] / (B_ * D_);
    float* out = (float*)d_out;
    const size_t TBN = (size_t)T * B_ * N_;
    const long long fullsz = (long long)B_ * O_ + 4LL * (long long)TBN;
    const int writeHist = ((long long)out_size >= fullsz) ? 1 : 0;
    float* spk = out + B_ * O_;
    float* vlt = spk + TBN;
    float* psc = vlt + TBN;
    float* flt = psc + TBN;

    const float e_syn = (float)exp((double)(-1.0f / 5.0f));
    const float e_asc = (float)exp((double)(-1.0f / 700.0f));
    const float alpha = (float)exp((double)(-1.0f / 20.0f));
    // int(T * (1.0 - 0.8)) truncates (float artifact): 199 for T=1000
    const int startT = (int)((double)T * (1.0 - 0.8));

    const int NG = (T / 2) * 4;                 // gemm CTAs (M-tiles x 4 N-tiles)
    const int grid = SIM_BLKS + NG + TP_BLKS;   // sim | gemm | transpose

    reset_kernel<<<1, 512>>>();

    cudaFuncSetAttribute(mega, cudaFuncAttributeMaxDynamicSharedMemorySize, GEMM_DSMEM);
    mega<<<grid, 256, GEMM_DSMEM>>>(x, Win, isc, Wrec, Wout, bout, osc,
                                    out, spk, vlt, psc, flt,
                                    T, startT, writeHist, e_syn, e_asc, alpha);
}